// round 16
// baseline (speedup 1.0000x reference)
#include <cuda_runtime.h>
#include <math.h>

#define NNODES 5120
#define NB     128
#define NPG    40
#define MAXN   45
#define LPROT  512
#define ROWSD  (NB*MAXN)
#define EMAX   20000

__device__ float d_deg [NNODES];
__device__ float d_dinv[NNODES];
__device__ float d_coef[EMAX];
__device__ float d_xw  [NNODES*256];
__device__ float d_h1  [NNODES*128];
__device__ float d_h2  [NNODES*128];
__device__ float d_h3  [NNODES*256];
__device__ float d_hd  [ROWSD*256];
__device__ float d_hd1 [ROWSD*1024];
__device__ float d_Xd  [ROWSD*128];
__device__ int   d_rep [NB];
__device__ float d_t1  [NB*LPROT*128];
__device__ float d_t2  [NB*LPROT*128];
__device__ float d_tb  [NB*LPROT*128];
__device__ float d_WptT[NB*LPROT*32];
__device__ float d_WcxT[NB*MAXN*32];
__device__ float d_Cm  [NB*LPROT*MAXN];
__device__ float d_CtM [NB*MAXN*LPROT];
__device__ float d_HcT [NB*MAXN*32];
__device__ float d_HpT [NB*LPROT*32];
__device__ float d_cp  [NB*256];
__device__ float d_f1  [NB*1024];
__device__ float d_f2  [NB*512];

// ---------- generic SGEMM: C = act(A@B + bias) ----------
// AMODE 0: plain. 2: A rows gathered from proteins (row m -> gidx[m>>9]*512*K + (m&511)*K),
//          skip blocks with rep[b]!=b. 3: plain A but skip duplicate-batch blocks.
template<int AMODE,int ACT,int BIAS>
__global__ void __launch_bounds__(256)
gemm_k(const float* __restrict__ A, const float* __restrict__ B,
       const float* __restrict__ bias, float* __restrict__ C,
       int M, int N, int K,
       const int* __restrict__ gidx, const int* __restrict__ rep)
{
    constexpr int BM=128, BN=128, BK=16, TM=8, TN=8;
    __shared__ float As[BK][BM];
    __shared__ float Bs[BK][BN];
    const int bm = blockIdx.x*BM;
    const int bn = blockIdx.y*BN;
    const int tid = threadIdx.x;

    long abase = 0; int lbase = 0;
    if (AMODE == 2) {
        int b = bm >> 9;
        if (rep[b] != b) return;
        abase = (long)gidx[b]*(long)512*(long)K;
        lbase = bm & 511;
    } else if (AMODE == 3) {
        int b = bm >> 9;
        if (rep[b] != b) return;
    }

    const int ty = tid/16, tx = tid%16;
    float acc[TM][TN];
    #pragma unroll
    for (int i=0;i<TM;i++)
        #pragma unroll
        for (int j=0;j<TN;j++) acc[i][j]=0.f;

    for (int k0=0;k0<K;k0+=BK){
        #pragma unroll
        for (int r=0;r<8;r++){
            int i = r*256 + tid;
            int m = i/BK, k = i%BK;
            int gm = bm+m, gk = k0+k;
            float v = 0.f;
            if (gm<M && gk<K){
                if (AMODE==2) v = A[abase + (long)(lbase+m)*K + gk];
                else          v = A[(long)gm*K + gk];
            }
            As[k][m] = v;
        }
        #pragma unroll
        for (int r=0;r<8;r++){
            int i = r*256 + tid;
            int k = i/BN, n = i%BN;
            int gk = k0+k, gn = bn+n;
            Bs[k][n] = (gk<K && gn<N) ? B[(long)gk*N + gn] : 0.f;
        }
        __syncthreads();
        #pragma unroll
        for (int k=0;k<BK;k++){
            float a[TM], bv[TN];
            #pragma unroll
            for (int i=0;i<TM;i++) a[i]  = As[k][ty*TM+i];
            #pragma unroll
            for (int j=0;j<TN;j++) bv[j] = Bs[k][tx*TN+j];
            #pragma unroll
            for (int i=0;i<TM;i++)
                #pragma unroll
                for (int j=0;j<TN;j++) acc[i][j] += a[i]*bv[j];
        }
        __syncthreads();
    }
    #pragma unroll
    for (int i=0;i<TM;i++){
        int gm = bm+ty*TM+i;
        if (gm >= M) continue;
        #pragma unroll
        for (int j=0;j<TN;j++){
            int gn = bn+tx*TN+j;
            if (gn >= N) continue;
            float v = acc[i][j];
            if (BIAS) v += bias[gn];
            if (ACT==1) v = fmaxf(v,0.f);
            C[(long)gm*N + gn] = v;
        }
    }
}

// ---------- batched GEMM: C[b] = act((ADD?P:0) + A[b]@op(B[b])) ----------
// TRANSB=1: B is [Mb,K]; TRANSB=0: B is [K,Mb]. rep* flags index via rep[b].
// Optional transposed copy into Ct [Mb,Ma] with ld=ldCt.
template<int TRANSB,int ACT,int ADD,int SKIP>
__global__ void __launch_bounds__(256)
bgemm_k(const float* __restrict__ A, long sA, int repA,
        const float* __restrict__ Bm, long sB, int repB,
        const float* __restrict__ P,  long sP, int repP,
        float* __restrict__ C, long sC,
        float* __restrict__ Ct, int ldCt, long sCt,
        int Ma, int Mb, int K, const int* __restrict__ rep)
{
    constexpr int BM=64,BN=64,BK=16,TM=4,TN=4;
    __shared__ float As[BK][BM];
    __shared__ float Bs[BK][BN];
    const int b = blockIdx.z;
    if (SKIP) { if (rep[b] != b) return; }
    const float* Ab = A  + sA*(long)(repA ? rep[b] : b);
    const float* Bb = Bm + sB*(long)(repB ? rep[b] : b);
    float* Cb  = C + sC*(long)b;
    float* Ctb = Ct ? (Ct + sCt*(long)b) : (float*)0;

    const int bm = blockIdx.x*BM;
    const int bn = blockIdx.y*BN;
    const int tid = threadIdx.x;
    const int ty = tid/16, tx = tid%16;

    float acc[TM][TN];
    #pragma unroll
    for (int i=0;i<TM;i++)
        #pragma unroll
        for (int j=0;j<TN;j++) acc[i][j]=0.f;

    for (int k0=0;k0<K;k0+=BK){
        #pragma unroll
        for (int r=0;r<4;r++){
            int i = r*256 + tid;
            int m = i/BK, k = i%BK;
            int gm = bm+m, gk = k0+k;
            As[k][m] = (gm<Ma && gk<K) ? Ab[(long)gm*K + gk] : 0.f;
        }
        #pragma unroll
        for (int r=0;r<4;r++){
            int i = r*256 + tid;
            float v = 0.f;
            if (TRANSB){
                int n = i/BK, k = i%BK;
                int gn = bn+n, gk = k0+k;
                if (gn<Mb && gk<K) v = Bb[(long)gn*K + gk];
                Bs[k][n] = v;
            } else {
                int k = i/BN, n = i%BN;
                int gk = k0+k, gn = bn+n;
                if (gk<K && gn<Mb) v = Bb[(long)gk*Mb + gn];
                Bs[k][n] = v;
            }
        }
        __syncthreads();
        #pragma unroll
        for (int k=0;k<BK;k++){
            float a[TM], bv[TN];
            #pragma unroll
            for (int i=0;i<TM;i++) a[i]  = As[k][ty*TM+i];
            #pragma unroll
            for (int j=0;j<TN;j++) bv[j] = Bs[k][tx*TN+j];
            #pragma unroll
            for (int i=0;i<TM;i++)
                #pragma unroll
                for (int j=0;j<TN;j++) acc[i][j] += a[i]*bv[j];
        }
        __syncthreads();
    }
    const float* Pb = ADD ? (P + sP*(long)(repP ? rep[b] : b)) : (const float*)0;
    #pragma unroll
    for (int i=0;i<TM;i++){
        int gm = bm+ty*TM+i;
        if (gm >= Ma) continue;
        #pragma unroll
        for (int j=0;j<TN;j++){
            int gn = bn+tx*TN+j;
            if (gn >= Mb) continue;
            float v = acc[i][j];
            if (ADD) v += Pb[(long)gm*Mb + gn];
            if (ACT==2) v = tanhf(v);
            Cb[(long)gm*Mb + gn] = v;
            if (Ctb) Ctb[(long)gn*ldCt + gm] = v;
        }
    }
}

// ---------- GCN helpers ----------
__global__ void deg_init(float* deg){ int i=blockIdx.x*blockDim.x+threadIdx.x; if(i<NNODES) deg[i]=1.f; }
__global__ void deg_acc(float* deg, const int* __restrict__ dst, int E){
    int e=blockIdx.x*blockDim.x+threadIdx.x; if(e<E) atomicAdd(&deg[dst[e]],1.f);
}
__global__ void deg_inv(float* dinv, const float* __restrict__ deg){
    int i=blockIdx.x*blockDim.x+threadIdx.x; if(i<NNODES) dinv[i]=rsqrtf(deg[i]);
}
__global__ void edge_coef(float* coef, const float* __restrict__ dinv,
                          const int* __restrict__ src, const int* __restrict__ dst, int E){
    int e=blockIdx.x*blockDim.x+threadIdx.x; if(e<E) coef[e]=dinv[src[e]]*dinv[dst[e]];
}
template<int F>
__global__ void gcn_combine(float* __restrict__ h, const float* __restrict__ xw,
                            const float* __restrict__ bias, const float* __restrict__ dinv){
    int idx=blockIdx.x*blockDim.x+threadIdx.x;
    if (idx>=NNODES*F) return;
    int i=idx/F, f=idx%F;
    float di=dinv[i];
    h[idx] = xw[idx]*di*di + bias[f];
}
template<int F>
__global__ void gcn_scatter(float* __restrict__ agg, const float* __restrict__ xw,
                            const float* __restrict__ coef,
                            const int* __restrict__ src, const int* __restrict__ dst, int E){
    long idx=(long)blockIdx.x*blockDim.x+threadIdx.x;
    if (idx>=(long)E*F) return;
    int e=(int)(idx/F), f=(int)(idx%F);
    atomicAdd(&agg[(long)dst[e]*F+f], coef[e]*xw[(long)src[e]*F+f]);
}
__global__ void relu_k(float* x, long n){
    long i=(long)blockIdx.x*blockDim.x+threadIdx.x;
    if (i<n) x[i]=fmaxf(x[i],0.f);
}
__global__ void dense_batch(float* __restrict__ dense, const float* __restrict__ h3){
    int idx=blockIdx.x*blockDim.x+threadIdx.x;
    if (idx>=ROWSD*256) return;
    int row=idx/256, f=idx%256;
    int g=row/MAXN, p=row%MAXN;
    dense[idx] = (p<NPG) ? h3[(g*NPG+p)*256+f] : 0.f;
}
__global__ void rep_k(int* rep, const int* __restrict__ tids){
    int b=threadIdx.x;
    int t=tids[b]; int r=b;
    for (int j=0;j<b;j++) if (tids[j]==t){ r=j; break; }
    rep[b]=r;
}

// ---------- attention pool ----------
__global__ void __launch_bounds__(256)
attn_pool(const float* __restrict__ HcT, const float* __restrict__ HpT,
          const float* __restrict__ Xd,  const float* __restrict__ t2,
          const float* __restrict__ whc, const float* __restrict__ whp,
          const int* __restrict__ rep, float* __restrict__ cp)
{
    int b=blockIdx.x, t=threadIdx.x;
    __shared__ float lc[MAXN], lp[LPROT], red[256], wc[32], wp[32];
    if (t<32){ wc[t]=whc[t]; wp[t]=whp[t]; }
    __syncthreads();
    if (t<MAXN){
        const float* h = HcT + ((long)b*MAXN + t)*32; float s=0;
        #pragma unroll
        for (int k=0;k<32;k++) s+=wc[k]*h[k];
        lc[t]=s;
    }
    for (int l=t;l<LPROT;l+=256){
        const float* h = HpT + ((long)b*LPROT + l)*32; float s=0;
        #pragma unroll
        for (int k=0;k<32;k++) s+=wp[k]*h[k];
        lp[l]=s;
    }
    __syncthreads();
    // softmax over lp (512), parallel
    float pm=-1e30f;
    for (int l=t;l<LPROT;l+=256) pm=fmaxf(pm,lp[l]);
    red[t]=pm; __syncthreads();
    for (int off=128;off>0;off>>=1){ if(t<off) red[t]=fmaxf(red[t],red[t+off]); __syncthreads(); }
    pm=red[0]; __syncthreads();
    float ps=0;
    for (int l=t;l<LPROT;l+=256){ float e=expf(lp[l]-pm); lp[l]=e; ps+=e; }
    red[t]=ps; __syncthreads();
    for (int off=128;off>0;off>>=1){ if(t<off) red[t]+=red[t+off]; __syncthreads(); }
    float inv=1.f/red[0];
    for (int l=t;l<LPROT;l+=256) lp[l]*=inv;
    // softmax over lc (45), serial by thread 0
    if (t==0){
        float m=lc[0];
        for (int i=1;i<MAXN;i++) m=fmaxf(m,lc[i]);
        float ss=0;
        for (int i=0;i<MAXN;i++){ float e=expf(lc[i]-m); lc[i]=e; ss+=e; }
        float iv=1.f/ss;
        for (int i=0;i<MAXN;i++) lc[i]*=iv;
    }
    __syncthreads();
    if (t<128){
        const float* X = Xd + (long)b*MAXN*128;
        float s=0;
        for (int si=0;si<MAXN;si++) s += lc[si]*X[si*128+t];
        cp[b*256+t]=s;
    } else {
        int m=t-128;
        const float* T = t2 + (long)rep[b]*LPROT*128;
        float s=0;
        for (int l=0;l<LPROT;l++) s += lp[l]*T[l*128+m];
        cp[b*256+128+m]=s;
    }
}

__global__ void out_k(const float* __restrict__ f2, const float* __restrict__ W,
                      const float* __restrict__ ob, float* __restrict__ out){
    int b=blockIdx.x, t=threadIdx.x; // 128 threads
    float s=0;
    for (int k=t;k<512;k+=128) s += f2[b*512+k]*W[k];
    __shared__ float red[128];
    red[t]=s; __syncthreads();
    for (int off=64;off>0;off>>=1){ if(t<off) red[t]+=red[t+off]; __syncthreads(); }
    if (t==0) out[b]=red[0]+ob[0];
}

static float* gp(void* const* d, int i){ return (float*)d[i]; }

extern "C" void kernel_launch(void* const* d_in, const int* in_sizes, int n_in,
                              void* d_out, int out_size)
{
    const float* x     = gp(d_in,0);
    const int*   ei    = (const int*)d_in[1];
    const int*   tid_  = (const int*)d_in[2];
    const float* prot  = gp(d_in,4);
    const float *gW1=gp(d_in,5), *gb1=gp(d_in,6), *gW2=gp(d_in,7), *gb2=gp(d_in,8);
    const float *gW3=gp(d_in,9), *gb3=gp(d_in,10);
    const float *fc1W=gp(d_in,11), *fc1b=gp(d_in,12), *fc2W=gp(d_in,13), *fc2b=gp(d_in,14);
    const float *b1W=gp(d_in,15), *b1b=gp(d_in,16), *b2W=gp(d_in,17), *b2b=gp(d_in,18);
    const float *Wb=gp(d_in,19), *Wc=gp(d_in,20), *Wp=gp(d_in,21);
    const float *whc=gp(d_in,22), *whp=gp(d_in,23);
    const float *c1W=gp(d_in,24), *c1b=gp(d_in,25), *c2W=gp(d_in,26), *c2b=gp(d_in,27);
    const float *oW=gp(d_in,28), *ob=gp(d_in,29);
    float* out = (float*)d_out;

    const int E = in_sizes[1]/2;
    const int* src = ei;
    const int* dst = ei + E;

    float *deg,*dinv,*coef,*xw,*h1,*h2,*h3,*hd,*hd1,*Xd,*t1,*t2,*tb,*WptT,*WcxT,*Cm,*CtM,*HcT,*HpT,*cp,*f1,*f2;
    int* rep;
    cudaGetSymbolAddress((void**)&deg,d_deg);   cudaGetSymbolAddress((void**)&dinv,d_dinv);
    cudaGetSymbolAddress((void**)&coef,d_coef); cudaGetSymbolAddress((void**)&xw,d_xw);
    cudaGetSymbolAddress((void**)&h1,d_h1);     cudaGetSymbolAddress((void**)&h2,d_h2);
    cudaGetSymbolAddress((void**)&h3,d_h3);     cudaGetSymbolAddress((void**)&hd,d_hd);
    cudaGetSymbolAddress((void**)&hd1,d_hd1);   cudaGetSymbolAddress((void**)&Xd,d_Xd);
    cudaGetSymbolAddress((void**)&rep,d_rep);   cudaGetSymbolAddress((void**)&t1,d_t1);
    cudaGetSymbolAddress((void**)&t2,d_t2);     cudaGetSymbolAddress((void**)&tb,d_tb);
    cudaGetSymbolAddress((void**)&WptT,d_WptT); cudaGetSymbolAddress((void**)&WcxT,d_WcxT);
    cudaGetSymbolAddress((void**)&Cm,d_Cm);     cudaGetSymbolAddress((void**)&CtM,d_CtM);
    cudaGetSymbolAddress((void**)&HcT,d_HcT);   cudaGetSymbolAddress((void**)&HpT,d_HpT);
    cudaGetSymbolAddress((void**)&cp,d_cp);     cudaGetSymbolAddress((void**)&f1,d_f1);
    cudaGetSymbolAddress((void**)&f2,d_f2);

    // degree / normalization
    deg_init<<<(NNODES+255)/256,256>>>(deg);
    deg_acc<<<(E+255)/256,256>>>(deg,dst,E);
    deg_inv<<<(NNODES+255)/256,256>>>(dinv,deg);
    edge_coef<<<(E+255)/256,256>>>(coef,dinv,src,dst,E);

    // GCN layer 1 (78->128)
    gemm_k<0,0,0><<<dim3(40,1),256>>>(x,gW1,0,xw,NNODES,128,78,0,0);
    gcn_combine<128><<<(NNODES*128+255)/256,256>>>(h1,xw,gb1,dinv);
    gcn_scatter<128><<<(int)(((long)E*128+255)/256),256>>>(h1,xw,coef,src,dst,E);
    relu_k<<<(NNODES*128+255)/256,256>>>(h1,(long)NNODES*128);
    // GCN layer 2 (128->128)
    gemm_k<0,0,0><<<dim3(40,1),256>>>(h1,gW2,0,xw,NNODES,128,128,0,0);
    gcn_combine<128><<<(NNODES*128+255)/256,256>>>(h2,xw,gb2,dinv);
    gcn_scatter<128><<<(int)(((long)E*128+255)/256),256>>>(h2,xw,coef,src,dst,E);
    relu_k<<<(NNODES*128+255)/256,256>>>(h2,(long)NNODES*128);
    // GCN layer 3 (128->256)
    gemm_k<0,0,0><<<dim3(40,2),256>>>(h2,gW3,0,xw,NNODES,256,128,0,0);
    gcn_combine<256><<<(NNODES*256+255)/256,256>>>(h3,xw,gb3,dinv);
    gcn_scatter<256><<<(int)(((long)E*256+255)/256),256>>>(h3,xw,coef,src,dst,E);
    relu_k<<<(NNODES*256+255)/256,256>>>(h3,(long)NNODES*256);

    // dense batch + fc1/fc2
    dense_batch<<<(ROWSD*256+255)/256,256>>>(hd,h3);
    gemm_k<0,1,1><<<dim3(45,8),256>>>(hd,fc1W,fc1b,hd1,ROWSD,1024,256,0,0);
    gemm_k<0,1,1><<<dim3(45,1),256>>>(hd1,fc2W,fc2b,Xd,ROWSD,128,1024,0,0);

    // protein dedup + bert stack (dedup-skipped)
    rep_k<<<1,NB>>>(rep,tid_);
    gemm_k<2,1,1><<<dim3(512,1),256>>>(prot,b1W,b1b,t1,NB*LPROT,128,1280,tid_,rep);
    gemm_k<3,1,1><<<dim3(512,1),256>>>(t1,b2W,b2b,t2,NB*LPROT,128,128,0,rep);
    gemm_k<3,0,0><<<dim3(512,1),256>>>(t2,Wb,0,tb,NB*LPROT,128,128,0,rep);

    // co-attention
    bgemm_k<1,0,0,1><<<dim3(8,1,NB),256>>>(t2,(long)LPROT*128,0, Wp,0,0, 0,0,0,
        WptT,(long)LPROT*32, 0,0,0, LPROT,32,128, rep);
    bgemm_k<1,0,0,0><<<dim3(1,1,NB),256>>>(Xd,(long)MAXN*128,0, Wc,0,0, 0,0,0,
        WcxT,(long)MAXN*32, 0,0,0, MAXN,32,128, rep);
    bgemm_k<1,2,0,0><<<dim3(8,1,NB),256>>>(tb,(long)LPROT*128,1, Xd,(long)MAXN*128,0, 0,0,0,
        Cm,(long)LPROT*MAXN, CtM,LPROT,(long)MAXN*LPROT, LPROT,MAXN,128, rep);
    bgemm_k<0,2,1,0><<<dim3(1,1,NB),256>>>(CtM,(long)MAXN*LPROT,0, WptT,(long)LPROT*32,1,
        WcxT,(long)MAXN*32,0, HcT,(long)MAXN*32, 0,0,0, MAXN,32,LPROT, rep);
    bgemm_k<0,2,1,0><<<dim3(8,1,NB),256>>>(Cm,(long)LPROT*MAXN,0, WcxT,(long)MAXN*32,0,
        WptT,(long)LPROT*32,1, HpT,(long)LPROT*32, 0,0,0, LPROT,32,MAXN, rep);

    attn_pool<<<NB,256>>>(HcT,HpT,Xd,t2,whc,whp,rep,cp);

    // head MLP
    gemm_k<0,1,1><<<dim3(1,8),256>>>(cp,c1W,c1b,f1,NB,1024,256,0,0);
    gemm_k<0,1,1><<<dim3(1,4),256>>>(f1,c2W,c2b,f2,NB,512,1024,0,0);
    out_k<<<NB,128>>>(f2,oW,ob,out);
}